// round 11
// baseline (speedup 1.0000x reference)
#include <cuda_runtime.h>
#include <cuda_fp16.h>
#include <mma.h>
#include <math.h>
#include <stdint.h>

using namespace nvcuda;

// ---------------- problem constants ----------------
#define NB     16
#define NTOK   1024
#define HEADS  8
#define DHEAD  64
#define INNER  512
#define QKVC   1536
#define NNSQ   (NTOK * NTOK)
#define MTOT   (NB * NTOK)          // 16384
#define ATT_SCALE 0.125f

// ---------------- device scratch ----------------
__device__ __half g_xh   [(size_t)MTOT * INNER];
__device__ __half g_wqkvh[(size_t)INNER * QKVC];
__device__ __half g_wouth[(size_t)INNER * INNER];
__device__ __half g_qkvh [(size_t)MTOT * QKVC];
__device__ __half g_biash[(size_t)HEADS * NNSQ];
__device__ __half g_atth [(size_t)MTOT * INNER];

// ---------------- async copy helpers ----------------
#define CP_ASYNC16(sa, ga) \
    asm volatile("cp.async.cg.shared.global [%0], [%1], 16;" \
                 :: "r"(sa), "l"(ga) : "memory")
#define CP_COMMIT()  asm volatile("cp.async.commit_group;" ::: "memory")
#define CP_WAIT0()   asm volatile("cp.async.wait_group 0;" ::: "memory")
#define CP_WAIT1()   asm volatile("cp.async.wait_group 1;" ::: "memory")

__device__ __forceinline__ uint32_t s2u(const void* p) {
    return (uint32_t)__cvta_generic_to_shared(p);
}
__device__ __forceinline__ void ldsm_x4(uint32_t* r, uint32_t addr) {
    asm volatile("ldmatrix.sync.aligned.m8n8.x4.shared.b16 {%0,%1,%2,%3}, [%4];"
                 : "=r"(r[0]), "=r"(r[1]), "=r"(r[2]), "=r"(r[3]) : "r"(addr));
}
__device__ __forceinline__ void ldsm_x4_t(uint32_t* r, uint32_t addr) {
    asm volatile("ldmatrix.sync.aligned.m8n8.x4.trans.shared.b16 {%0,%1,%2,%3}, [%4];"
                 : "=r"(r[0]), "=r"(r[1]), "=r"(r[2]), "=r"(r[3]) : "r"(addr));
}
__device__ __forceinline__ void mma16816(float* d, const uint32_t* a, const uint32_t* b) {
    asm volatile(
        "mma.sync.aligned.m16n8k16.row.col.f32.f16.f16.f32 "
        "{%0,%1,%2,%3}, {%4,%5,%6,%7}, {%8,%9}, {%0,%1,%2,%3};"
        : "+f"(d[0]), "+f"(d[1]), "+f"(d[2]), "+f"(d[3])
        : "r"(a[0]), "r"(a[1]), "r"(a[2]), "r"(a[3]), "r"(b[0]), "r"(b[1]));
}

// ---------------- prep kernels ----------------
__global__ void convert_x_kernel(const float* __restrict__ x) {
    size_t i = (size_t)blockIdx.x * 256 + threadIdx.x;
    float2 v = ((const float2*)x)[i];
    ((__half2*)g_xh)[i] = __floats2half2_rn(v.x, v.y);
}
__global__ void convert_w_kernel(const float* __restrict__ W, __half* __restrict__ Wh,
                                 int total) {
    int i = blockIdx.x * 256 + threadIdx.x;
    if (i < total) Wh[i] = __float2half(W[i]);
}
__global__ void bias_kernel(const int* __restrict__ ri, const float* __restrict__ rt) {
    int t = blockIdx.x * 256 + threadIdx.x;
    int idx = ri[t];
    #pragma unroll
    for (int h = 0; h < HEADS; h++)
        g_biash[(size_t)h * NNSQ + t] = __float2half(rt[idx * HEADS + h]);
}

// ---------------- wmma GEMM, cp.async double-buffered ----------------
// CTA tile 128x128, BK=64, 8 warps (4 x 2), warp tile 32x64. Dynamic smem.
#define ALD 72
#define BLD 136
#define AS_STAGE (128 * ALD)      // halfs
#define BS_STAGE (64 * BLD)
#define GEMM_SMEM ((2 * AS_STAGE + 2 * BS_STAGE) * 2)   // bytes = 71680

__global__ __launch_bounds__(256)
void gemm_wmma_kernel(const __half* __restrict__ A, const __half* __restrict__ B,
                      __half* __restrict__ Ch, float* __restrict__ Cf,
                      const float* __restrict__ bias, int Nn, int K, int outHalf) {
    extern __shared__ __half sm[];
    __half* As = sm;                       // 2 stages
    __half* Bs = sm + 2 * AS_STAGE;        // 2 stages
    float*  buf = (float*)sm;              // epilogue staging (aliases As; used after sync)

    const int tid = threadIdx.x, wid = tid >> 5, lane = tid & 31;
    const int wm = wid & 3, wn = wid >> 2;
    const int m0 = blockIdx.y * 128, n0 = blockIdx.x * 128;
    const int nStages = K / 64;

    wmma::fragment<wmma::accumulator, 16, 16, 16, float> c[2][4];
    #pragma unroll
    for (int i = 0; i < 2; i++)
        #pragma unroll
        for (int j = 0; j < 4; j++) wmma::fill_fragment(c[i][j], 0.0f);

    // async tile loaders
    auto loadTiles = [&](int s, int kb) {
        __half* as = As + s * AS_STAGE;
        __half* bs = Bs + s * BS_STAGE;
        #pragma unroll
        for (int i = tid; i < 1024; i += 256) {
            int r = i >> 3, cc = (i & 7) * 8;
            CP_ASYNC16(s2u(as + r * ALD + cc),
                       A + (size_t)(m0 + r) * K + kb + cc);
        }
        #pragma unroll
        for (int i = tid; i < 1024; i += 256) {
            int r = i >> 4, cc = (i & 15) * 8;
            CP_ASYNC16(s2u(bs + r * BLD + cc),
                       B + (size_t)(kb + r) * Nn + n0 + cc);
        }
        CP_COMMIT();
    };

    loadTiles(0, 0);
    for (int s = 0; s < nStages; s++) {
        if (s + 1 < nStages) { loadTiles((s + 1) & 1, (s + 1) * 64); CP_WAIT1(); }
        else                 { CP_WAIT0(); }
        __syncthreads();
        const __half* as = As + (s & 1) * AS_STAGE;
        const __half* bs = Bs + (s & 1) * BS_STAGE;
        #pragma unroll
        for (int kk = 0; kk < 4; kk++) {
            wmma::fragment<wmma::matrix_a, 16, 16, 16, __half, wmma::row_major> a[2];
            wmma::fragment<wmma::matrix_b, 16, 16, 16, __half, wmma::row_major> bfr[4];
            #pragma unroll
            for (int i = 0; i < 2; i++)
                wmma::load_matrix_sync(a[i], &as[(wm * 32 + i * 16) * ALD + kk * 16], ALD);
            #pragma unroll
            for (int j = 0; j < 4; j++)
                wmma::load_matrix_sync(bfr[j], &bs[(kk * 16) * BLD + wn * 64 + j * 16], BLD);
            #pragma unroll
            for (int i = 0; i < 2; i++)
                #pragma unroll
                for (int j = 0; j < 4; j++)
                    wmma::mma_sync(c[i][j], a[i], bfr[j], c[i][j]);
        }
        __syncthreads();
    }

    // epilogue via per-warp smem staging (aliased over As)
    float* mybuf = buf + wid * 16 * 20;
    #pragma unroll
    for (int i = 0; i < 2; i++) {
        #pragma unroll
        for (int j = 0; j < 4; j++) {
            wmma::store_matrix_sync(mybuf, c[i][j], 20, wmma::mem_row_major);
            __syncwarp();
            int r   = lane >> 1;
            int cl  = (lane & 1) * 8;
            int row = m0 + wm * 32 + i * 16 + r;
            int col = n0 + wn * 64 + j * 16 + cl;
            const float* src = &mybuf[r * 20 + cl];
            if (outHalf) {
                __half2 h2[4];
                #pragma unroll
                for (int q = 0; q < 4; q++)
                    h2[q] = __floats2half2_rn(src[2 * q], src[2 * q + 1]);
                *(float4*)(Ch + (size_t)row * Nn + col) = *(float4*)h2;
            } else {
                float v[8];
                #pragma unroll
                for (int q = 0; q < 8; q++) v[q] = src[q] + bias[col + q];
                float* dst = Cf + (size_t)row * Nn + col;
                *(float4*)dst = *(float4*)v;
                *(float4*)(dst + 4) = *(float4*)(v + 4);
            }
            __syncwarp();
        }
    }
}

// ---------------- flash attention: 128-row Q tile, ldmatrix, cp.async ----------------
// grid (8 qtiles, 8 heads, 16 batch), 256 threads (8 warps, 16 q-rows each).
#define KLD 72

__global__ __launch_bounds__(256)
void attn_mma_kernel() {
    __shared__ __half Ks[2][64 * KLD];
    __shared__ __half Vs[2][64 * KLD];

    const int qt = blockIdx.x, h = blockIdx.y, b = blockIdx.z;
    const int q0 = qt * 128;
    const int tid = threadIdx.x, wq = tid >> 5, lane = tid & 31;
    const int g = lane >> 2, tig = lane & 3;

    // ---- Q fragments (A operand) from gmem ----
    uint32_t aQ[4][4];
    {
        const __half* q0p = g_qkvh + (size_t)(b * NTOK + q0 + wq * 16 + g) * QKVC + h * DHEAD;
        const __half* q8p = q0p + (size_t)8 * QKVC;
        #pragma unroll
        for (int kc = 0; kc < 4; kc++) {
            aQ[kc][0] = *(const uint32_t*)(q0p + kc * 16 + tig * 2);
            aQ[kc][1] = *(const uint32_t*)(q8p + kc * 16 + tig * 2);
            aQ[kc][2] = *(const uint32_t*)(q0p + kc * 16 + 8 + tig * 2);
            aQ[kc][3] = *(const uint32_t*)(q8p + kc * 16 + 8 + tig * 2);
        }
    }

    float o[8][4];
    #pragma unroll
    for (int i = 0; i < 8; i++)
        #pragma unroll
        for (int j = 0; j < 4; j++) o[i][j] = 0.f;
    float l0 = 0.f, l1 = 0.f;

    const __half* bias0 = g_biash + ((size_t)h << 20)
                        + (size_t)(q0 + wq * 16 + g) * NTOK;
    const __half* bias8 = bias0 + (size_t)8 * NTOK;

    // ldmatrix lane addresses (constant across tiles, per stage)
    // K (non-trans): row = n0 + (lane&7) + (lane>>4)*8, colHalf = kc*16 + ((lane>>3)&1)*8
    const int kRow = (lane & 7) + ((lane >> 4) << 3);
    const int kColH = ((lane >> 3) & 1) * 8;
    // V (trans): row = kc*16 + ((lane>>3)&1)*8 + (lane&7), colHalf = d0 + (lane>>4)*8
    const int vRowOff = ((lane >> 3) & 1) * 8 + (lane & 7);
    const int vColH = (lane >> 4) * 8;

    auto ldKV = [&](int s, int k0) {
        #pragma unroll
        for (int i = tid; i < 512; i += 256) {
            int r = i >> 3, cc = (i & 7) * 8;
            const __half* gk = g_qkvh + (size_t)(b * NTOK + k0 + r) * QKVC
                             + INNER + h * DHEAD + cc;
            CP_ASYNC16(s2u(&Ks[s][r * KLD + cc]), gk);
            CP_ASYNC16(s2u(&Vs[s][r * KLD + cc]), gk + INNER);
        }
        CP_COMMIT();
    };

    ldKV(0, 0);
    for (int kt = 0; kt < 16; kt++) {
        const int k0 = kt * 64;
        if (kt + 1 < 16) { ldKV((kt + 1) & 1, (kt + 1) * 64); CP_WAIT1(); }
        else             { CP_WAIT0(); }
        __syncthreads();
        const int s = kt & 1;

        // ---- S = Q @ K^T ----
        float cS[8][4];
        #pragma unroll
        for (int nt = 0; nt < 8; nt++)
            #pragma unroll
            for (int j = 0; j < 4; j++) cS[nt][j] = 0.f;

        #pragma unroll
        for (int kc = 0; kc < 4; kc++) {
            #pragma unroll
            for (int nt2 = 0; nt2 < 4; nt2++) {
                uint32_t r4[4];
                ldsm_x4(r4, s2u(&Ks[s][(nt2 * 16 + kRow) * KLD + kc * 16 + kColH]));
                mma16816(cS[nt2 * 2],     aQ[kc], r4);
                mma16816(cS[nt2 * 2 + 1], aQ[kc], r4 + 2);
            }
        }

        // ---- scale + bias + exp, pack P A-fragments ----
        uint32_t pa[4][4];
        #pragma unroll
        for (int nt = 0; nt < 8; nt++) {
            __half2 b0 = *(const __half2*)(bias0 + k0 + nt * 8 + tig * 2);
            __half2 b8 = *(const __half2*)(bias8 + k0 + nt * 8 + tig * 2);
            float e0 = __expf(cS[nt][0] * ATT_SCALE + __low2float(b0));
            float e1 = __expf(cS[nt][1] * ATT_SCALE + __high2float(b0));
            float e2 = __expf(cS[nt][2] * ATT_SCALE + __low2float(b8));
            float e3 = __expf(cS[nt][3] * ATT_SCALE + __high2float(b8));
            l0 += e0 + e1;
            l1 += e2 + e3;
            __half2 p01 = __floats2half2_rn(e0, e1);
            __half2 p23 = __floats2half2_rn(e2, e3);
            pa[nt >> 1][(nt & 1) * 2 + 0] = *(uint32_t*)&p01;
            pa[nt >> 1][(nt & 1) * 2 + 1] = *(uint32_t*)&p23;
        }

        // ---- O += P @ V ----
        #pragma unroll
        for (int kc = 0; kc < 4; kc++) {
            #pragma unroll
            for (int dt2 = 0; dt2 < 4; dt2++) {
                uint32_t r4[4];
                ldsm_x4_t(r4, s2u(&Vs[s][(kc * 16 + vRowOff) * KLD + dt2 * 16 + vColH]));
                mma16816(o[dt2 * 2],     pa[kc], r4);
                mma16816(o[dt2 * 2 + 1], pa[kc], r4 + 2);
            }
        }
        __syncthreads();
    }

    // ---- row sums across the 4 lanes of each group ----
    l0 += __shfl_xor_sync(0xffffffffu, l0, 1);
    l0 += __shfl_xor_sync(0xffffffffu, l0, 2);
    l1 += __shfl_xor_sync(0xffffffffu, l1, 1);
    l1 += __shfl_xor_sync(0xffffffffu, l1, 2);
    const float inv0 = 1.0f / l0, inv1 = 1.0f / l1;

    // ---- write O (fp16) ----
    __half* out0 = g_atth + (size_t)(b * NTOK + q0 + wq * 16 + g) * INNER + h * DHEAD;
    __half* out8 = out0 + (size_t)8 * INNER;
    #pragma unroll
    for (int dt = 0; dt < 8; dt++) {
        __half2 r0 = __floats2half2_rn(o[dt][0] * inv0, o[dt][1] * inv0);
        __half2 r8 = __floats2half2_rn(o[dt][2] * inv1, o[dt][3] * inv1);
        *(__half2*)(out0 + dt * 8 + tig * 2) = r0;
        *(__half2*)(out8 + dt * 8 + tig * 2) = r8;
    }
}

// ---------------- launch ----------------
extern "C" void kernel_launch(void* const* d_in, const int* in_sizes, int n_in,
                              void* d_out, int out_size) {
    const float* x         = (const float*)d_in[0];
    const float* Wqkv      = (const float*)d_in[1];
    const float* rel_table = (const float*)d_in[2];
    const float* Wout      = (const float*)d_in[3];
    const float* bout      = (const float*)d_in[4];
    const int*   rel_index = (const int*)d_in[5];
    float*       out       = (float*)d_out;

    __half *xh, *wqkvh, *wouth, *qkvh, *atth;
    cudaGetSymbolAddress((void**)&xh,    g_xh);
    cudaGetSymbolAddress((void**)&wqkvh, g_wqkvh);
    cudaGetSymbolAddress((void**)&wouth, g_wouth);
    cudaGetSymbolAddress((void**)&qkvh,  g_qkvh);
    cudaGetSymbolAddress((void**)&atth,  g_atth);

    convert_x_kernel<<<(MTOT * INNER / 2) / 256, 256>>>(x);
    convert_w_kernel<<<(INNER * QKVC + 255) / 256, 256>>>(Wqkv, wqkvh, INNER * QKVC);
    convert_w_kernel<<<(INNER * INNER + 255) / 256, 256>>>(Wout, wouth, INNER * INNER);
    bias_kernel<<<NNSQ / 256, 256>>>(rel_index, rel_table);

    cudaFuncSetAttribute(gemm_wmma_kernel,
                         cudaFuncAttributeMaxDynamicSharedMemorySize, GEMM_SMEM);

    // QKV GEMM: [16384,512] @ [512,1536] -> fp16
    {
        dim3 g(QKVC / 128, MTOT / 128);
        gemm_wmma_kernel<<<g, 256, GEMM_SMEM>>>(xh, wqkvh, qkvh, nullptr, nullptr,
                                                QKVC, INNER, 1);
    }
    // attention: 128-row Q tiles
    {
        dim3 g(NTOK / 128, HEADS, NB);
        attn_mma_kernel<<<g, 256>>>();
    }
    // out projection: [16384,512] @ [512,512] + bias -> fp32
    {
        dim3 g(INNER / 128, MTOT / 128);
        gemm_wmma_kernel<<<g, 256, GEMM_SMEM>>>(atth, wouth, nullptr, out, bout,
                                                INNER, INNER, 0);
    }
}

// round 13
// speedup vs baseline: 1.4876x; 1.4876x over previous
#include <cuda_runtime.h>
#include <cuda_fp16.h>
#include <mma.h>
#include <math.h>
#include <stdint.h>

using namespace nvcuda;

// ---------------- problem constants ----------------
#define NB     16
#define NTOK   1024
#define HEADS  8
#define DHEAD  64
#define INNER  512
#define QKVC   1536
#define NNSQ   (NTOK * NTOK)
#define MTOT   (NB * NTOK)          // 16384
#define SC_LOG2E 0.1803368801111243f   // 0.125 * log2(e)
#define LOG2E    1.4426950408889634f

// ---------------- device scratch ----------------
__device__ __half g_xh   [(size_t)MTOT * INNER];
__device__ __half g_wqkvh[(size_t)INNER * QKVC];
__device__ __half g_wouth[(size_t)INNER * INNER];
__device__ __half g_qkvh [(size_t)MTOT * QKVC];
__device__ __half g_biash[(size_t)HEADS * NNSQ];   // bias * log2(e), fp16
__device__ __half g_atth [(size_t)MTOT * INNER];

// ---------------- helpers ----------------
#define CP_ASYNC16(sa, ga) \
    asm volatile("cp.async.cg.shared.global [%0], [%1], 16;" \
                 :: "r"(sa), "l"(ga) : "memory")
#define CP_COMMIT()  asm volatile("cp.async.commit_group;" ::: "memory")
#define CP_WAIT0()   asm volatile("cp.async.wait_group 0;" ::: "memory")
#define CP_WAIT1()   asm volatile("cp.async.wait_group 1;" ::: "memory")

__device__ __forceinline__ uint32_t s2u(const void* p) {
    return (uint32_t)__cvta_generic_to_shared(p);
}
__device__ __forceinline__ void ldsm_x4(uint32_t* r, uint32_t addr) {
    asm volatile("ldmatrix.sync.aligned.m8n8.x4.shared.b16 {%0,%1,%2,%3}, [%4];"
                 : "=r"(r[0]), "=r"(r[1]), "=r"(r[2]), "=r"(r[3]) : "r"(addr));
}
__device__ __forceinline__ void ldsm_x4_t(uint32_t* r, uint32_t addr) {
    asm volatile("ldmatrix.sync.aligned.m8n8.x4.trans.shared.b16 {%0,%1,%2,%3}, [%4];"
                 : "=r"(r[0]), "=r"(r[1]), "=r"(r[2]), "=r"(r[3]) : "r"(addr));
}
__device__ __forceinline__ void mma16816(float* d, const uint32_t* a, const uint32_t* b) {
    asm volatile(
        "mma.sync.aligned.m16n8k16.row.col.f32.f16.f16.f32 "
        "{%0,%1,%2,%3}, {%4,%5,%6,%7}, {%8,%9}, {%0,%1,%2,%3};"
        : "+f"(d[0]), "+f"(d[1]), "+f"(d[2]), "+f"(d[3])
        : "r"(a[0]), "r"(a[1]), "r"(a[2]), "r"(a[3]), "r"(b[0]), "r"(b[1]));
}
__device__ __forceinline__ float ex2(float x) {
    float r;
    asm("ex2.approx.f32 %0, %1;" : "=f"(r) : "f"(x));
    return r;
}

// ---------------- prep kernels ----------------
__global__ void convert_x_kernel(const float* __restrict__ x) {
    size_t i = (size_t)blockIdx.x * 256 + threadIdx.x;
    float2 v = ((const float2*)x)[i];
    ((__half2*)g_xh)[i] = __floats2half2_rn(v.x, v.y);
}
__global__ void convert_w_kernel(const float* __restrict__ W, __half* __restrict__ Wh,
                                 int total) {
    int i = blockIdx.x * 256 + threadIdx.x;
    if (i < total) Wh[i] = __float2half(W[i]);
}
__global__ void bias_kernel(const int* __restrict__ ri, const float* __restrict__ rt) {
    int t = blockIdx.x * 256 + threadIdx.x;
    int idx = ri[t];
    #pragma unroll
    for (int h = 0; h < HEADS; h++)
        g_biash[(size_t)h * NNSQ + t] = __float2half(rt[idx * HEADS + h] * LOG2E);
}

// ---------------- wmma GEMM, 3-stage cp.async ring ----------------
// CTA tile 128x128, BK=64, 8 warps (4 x 2), warp tile 32x64.
#define ALD 72
#define BLD 136
#define AS_STAGE (128 * ALD)      // halfs
#define BS_STAGE (64 * BLD)
#define GEMM_SMEM (3 * (AS_STAGE + BS_STAGE) * 2)   // 107520 B

__global__ __launch_bounds__(256)
void gemm_wmma_kernel(const __half* __restrict__ A, const __half* __restrict__ B,
                      __half* __restrict__ Ch, float* __restrict__ Cf,
                      const float* __restrict__ bias, int Nn, int K, int outHalf) {
    extern __shared__ __half sm[];
    __half* As = sm;                       // 3 stages
    __half* Bs = sm + 3 * AS_STAGE;        // 3 stages
    float*  buf = (float*)sm;              // epilogue staging (aliases; after barrier)

    const int tid = threadIdx.x, wid = tid >> 5, lane = tid & 31;
    const int wm = wid & 3, wn = wid >> 2;
    const int m0 = blockIdx.y * 128, n0 = blockIdx.x * 128;
    const int nStages = K / 64;

    wmma::fragment<wmma::accumulator, 16, 16, 16, float> c[2][4];
    #pragma unroll
    for (int i = 0; i < 2; i++)
        #pragma unroll
        for (int j = 0; j < 4; j++) wmma::fill_fragment(c[i][j], 0.0f);

    auto loadTiles = [&](int st, int kb) {
        __half* as = As + st * AS_STAGE;
        __half* bs = Bs + st * BS_STAGE;
        #pragma unroll
        for (int i = tid; i < 1024; i += 256) {
            int r = i >> 3, cc = (i & 7) * 8;
            CP_ASYNC16(s2u(as + r * ALD + cc),
                       A + (size_t)(m0 + r) * K + kb + cc);
        }
        #pragma unroll
        for (int i = tid; i < 1024; i += 256) {
            int r = i >> 4, cc = (i & 15) * 8;
            CP_ASYNC16(s2u(bs + r * BLD + cc),
                       B + (size_t)(kb + r) * Nn + n0 + cc);
        }
        CP_COMMIT();
    };

    loadTiles(0, 0);
    loadTiles(1, 64);
    for (int s = 0; s < nStages; s++) {
        if (s + 1 < nStages) CP_WAIT1(); else CP_WAIT0();
        __syncthreads();
        if (s + 2 < nStages) loadTiles((s + 2) % 3, (s + 2) * 64);

        const __half* as = As + (s % 3) * AS_STAGE;
        const __half* bs = Bs + (s % 3) * BS_STAGE;
        #pragma unroll
        for (int kk = 0; kk < 4; kk++) {
            wmma::fragment<wmma::matrix_a, 16, 16, 16, __half, wmma::row_major> a[2];
            wmma::fragment<wmma::matrix_b, 16, 16, 16, __half, wmma::row_major> bfr[4];
            #pragma unroll
            for (int i = 0; i < 2; i++)
                wmma::load_matrix_sync(a[i], &as[(wm * 32 + i * 16) * ALD + kk * 16], ALD);
            #pragma unroll
            for (int j = 0; j < 4; j++)
                wmma::load_matrix_sync(bfr[j], &bs[(kk * 16) * BLD + wn * 64 + j * 16], BLD);
            #pragma unroll
            for (int i = 0; i < 2; i++)
                #pragma unroll
                for (int j = 0; j < 4; j++)
                    wmma::mma_sync(c[i][j], a[i], bfr[j], c[i][j]);
        }
    }
    __syncthreads();   // all MMA reads done before buf aliases As

    float* mybuf = buf + wid * 16 * 20;
    #pragma unroll
    for (int i = 0; i < 2; i++) {
        #pragma unroll
        for (int j = 0; j < 4; j++) {
            wmma::store_matrix_sync(mybuf, c[i][j], 20, wmma::mem_row_major);
            __syncwarp();
            int r   = lane >> 1;
            int cl  = (lane & 1) * 8;
            int row = m0 + wm * 32 + i * 16 + r;
            int col = n0 + wn * 64 + j * 16 + cl;
            const float* src = &mybuf[r * 20 + cl];
            if (outHalf) {
                __half2 h2[4];
                #pragma unroll
                for (int q = 0; q < 4; q++)
                    h2[q] = __floats2half2_rn(src[2 * q], src[2 * q + 1]);
                *(float4*)(Ch + (size_t)row * Nn + col) = *(float4*)h2;
            } else {
                float v[8];
                #pragma unroll
                for (int q = 0; q < 8; q++) v[q] = src[q] + bias[col + q];
                float* dst = Cf + (size_t)row * Nn + col;
                *(float4*)dst = *(float4*)v;
                *(float4*)(dst + 4) = *(float4*)(v + 4);
            }
            __syncwarp();
        }
    }
}

// ---------------- flash attention: 128-row Q, 3-stage KV ring ----------------
// grid (8 qtiles, 8 heads, 16 batch), 256 threads (8 warps, 16 q-rows each).
#define KLD 72
#define KV_STAGE (64 * KLD)                 // halfs
#define ATTN_SMEM (3 * 2 * KV_STAGE * 2)    // 55296 B

__global__ __launch_bounds__(256)
void attn_mma_kernel() {
    extern __shared__ __half asm_[];
    __half* Ks = asm_;                  // 3 stages
    __half* Vs = asm_ + 3 * KV_STAGE;   // 3 stages

    const int qt = blockIdx.x, h = blockIdx.y, b = blockIdx.z;
    const int q0 = qt * 128;
    const int tid = threadIdx.x, wq = tid >> 5, lane = tid & 31;
    const int g = lane >> 2, tig = lane & 3;

    // ---- Q fragments (A operand) from gmem ----
    uint32_t aQ[4][4];
    {
        const __half* q0p = g_qkvh + (size_t)(b * NTOK + q0 + wq * 16 + g) * QKVC + h * DHEAD;
        const __half* q8p = q0p + (size_t)8 * QKVC;
        #pragma unroll
        for (int kc = 0; kc < 4; kc++) {
            aQ[kc][0] = *(const uint32_t*)(q0p + kc * 16 + tig * 2);
            aQ[kc][1] = *(const uint32_t*)(q8p + kc * 16 + tig * 2);
            aQ[kc][2] = *(const uint32_t*)(q0p + kc * 16 + 8 + tig * 2);
            aQ[kc][3] = *(const uint32_t*)(q8p + kc * 16 + 8 + tig * 2);
        }
    }

    float o[8][4];
    #pragma unroll
    for (int i = 0; i < 8; i++)
        #pragma unroll
        for (int j = 0; j < 4; j++) o[i][j] = 0.f;
    float l0 = 0.f, l1 = 0.f;

    const __half* bias0 = g_biash + ((size_t)h << 20)
                        + (size_t)(q0 + wq * 16 + g) * NTOK;
    const __half* bias8 = bias0 + (size_t)8 * NTOK;

    const int kRow = (lane & 7) + ((lane >> 4) << 3);
    const int kColH = ((lane >> 3) & 1) * 8;
    const int vRowOff = ((lane >> 3) & 1) * 8 + (lane & 7);
    const int vColH = (lane >> 4) * 8;

    auto ldKV = [&](int st, int k0) {
        #pragma unroll
        for (int i = tid; i < 512; i += 256) {
            int r = i >> 3, cc = (i & 7) * 8;
            const __half* gk = g_qkvh + (size_t)(b * NTOK + k0 + r) * QKVC
                             + INNER + h * DHEAD + cc;
            CP_ASYNC16(s2u(&Ks[st * KV_STAGE + r * KLD + cc]), gk);
            CP_ASYNC16(s2u(&Vs[st * KV_STAGE + r * KLD + cc]), gk + INNER);
        }
        CP_COMMIT();
    };

    ldKV(0, 0);
    ldKV(1, 64);
    for (int kt = 0; kt < 16; kt++) {
        const int k0 = kt * 64;
        if (kt + 1 < 16) CP_WAIT1(); else CP_WAIT0();
        __syncthreads();
        if (kt + 2 < 16) ldKV((kt + 2) % 3, (kt + 2) * 64);
        const __half* ks = Ks + (kt % 3) * KV_STAGE;
        const __half* vs = Vs + (kt % 3) * KV_STAGE;

        // ---- prefetch bias (latency hides under MMA1) ----
        __half2 bb0[4], bb8[4];
        #pragma unroll
        for (int nt2 = 0; nt2 < 4; nt2++) {
            bb0[nt2] = *(const __half2*)(bias0 + k0 + nt2 * 16 + tig * 2);     // nt even part? no:
        }
        // (separate loads per 8-col group; keep original indexing)
        __half2 c0[8], c8[8];
        #pragma unroll
        for (int nt = 0; nt < 8; nt++) {
            c0[nt] = *(const __half2*)(bias0 + k0 + nt * 8 + tig * 2);
            c8[nt] = *(const __half2*)(bias8 + k0 + nt * 8 + tig * 2);
        }

        // ---- S = Q @ K^T ----
        float cS[8][4];
        #pragma unroll
        for (int nt = 0; nt < 8; nt++)
            #pragma unroll
            for (int j = 0; j < 4; j++) cS[nt][j] = 0.f;

        #pragma unroll
        for (int kc = 0; kc < 4; kc++) {
            #pragma unroll
            for (int nt2 = 0; nt2 < 4; nt2++) {
                uint32_t r4[4];
                ldsm_x4(r4, s2u(&ks[(nt2 * 16 + kRow) * KLD + kc * 16 + kColH]));
                mma16816(cS[nt2 * 2],     aQ[kc], r4);
                mma16816(cS[nt2 * 2 + 1], aQ[kc], r4 + 2);
            }
        }

        // ---- scale + bias + ex2, pack P A-fragments ----
        uint32_t pa[4][4];
        #pragma unroll
        for (int nt = 0; nt < 8; nt++) {
            float e0 = ex2(fmaf(cS[nt][0], SC_LOG2E, __low2float(c0[nt])));
            float e1 = ex2(fmaf(cS[nt][1], SC_LOG2E, __high2float(c0[nt])));
            float e2 = ex2(fmaf(cS[nt][2], SC_LOG2E, __low2float(c8[nt])));
            float e3 = ex2(fmaf(cS[nt][3], SC_LOG2E, __high2float(c8[nt])));
            l0 += e0 + e1;
            l1 += e2 + e3;
            __half2 p01 = __floats2half2_rn(e0, e1);
            __half2 p23 = __floats2half2_rn(e2, e3);
            pa[nt >> 1][(nt & 1) * 2 + 0] = *(uint32_t*)&p01;
            pa[nt >> 1][(nt & 1) * 2 + 1] = *(uint32_t*)&p23;
        }

        // ---- O += P @ V ----
        #pragma unroll
        for (int kc = 0; kc < 4; kc++) {
            #pragma unroll
            for (int dt2 = 0; dt2 < 4; dt2++) {
                uint32_t r4[4];
                ldsm_x4_t(r4, s2u(&vs[(kc * 16 + vRowOff) * KLD + dt2 * 16 + vColH]));
                mma16816(o[dt2 * 2],     pa[kc], r4);
                mma16816(o[dt2 * 2 + 1], pa[kc], r4 + 2);
            }
        }
    }

    // ---- row sums across the 4 lanes of each group ----
    l0 += __shfl_xor_sync(0xffffffffu, l0, 1);
    l0 += __shfl_xor_sync(0xffffffffu, l0, 2);
    l1 += __shfl_xor_sync(0xffffffffu, l1, 1);
    l1 += __shfl_xor_sync(0xffffffffu, l1, 2);
    const float inv0 = 1.0f / l0, inv1 = 1.0f / l1;

    // ---- write O (fp16) ----
    __half* out0 = g_atth + (size_t)(b * NTOK + q0 + wq * 16 + g) * INNER + h * DHEAD;
    __half* out8 = out0 + (size_t)8 * INNER;
    #pragma unroll
    for (int dt = 0; dt < 8; dt++) {
        __half2 r0 = __floats2half2_rn(o[dt][0] * inv0, o[dt][1] * inv0);
        __half2 r8 = __floats2half2_rn(o[dt][2] * inv1, o[dt][3] * inv1);
        *(__half2*)(out0 + dt * 8 + tig * 2) = r0;
        *(__half2*)(out8 + dt * 8 + tig * 2) = r8;
    }
}

// ---------------- launch ----------------
extern "C" void kernel_launch(void* const* d_in, const int* in_sizes, int n_in,
                              void* d_out, int out_size) {
    const float* x         = (const float*)d_in[0];
    const float* Wqkv      = (const float*)d_in[1];
    const float* rel_table = (const float*)d_in[2];
    const float* Wout      = (const float*)d_in[3];
    const float* bout      = (const float*)d_in[4];
    const int*   rel_index = (const int*)d_in[5];
    float*       out       = (float*)d_out;

    __half *xh, *wqkvh, *wouth, *qkvh, *atth;
    cudaGetSymbolAddress((void**)&xh,    g_xh);
    cudaGetSymbolAddress((void**)&wqkvh, g_wqkvh);
    cudaGetSymbolAddress((void**)&wouth, g_wouth);
    cudaGetSymbolAddress((void**)&qkvh,  g_qkvh);
    cudaGetSymbolAddress((void**)&atth,  g_atth);

    convert_x_kernel<<<(MTOT * INNER / 2) / 256, 256>>>(x);
    convert_w_kernel<<<(INNER * QKVC + 255) / 256, 256>>>(Wqkv, wqkvh, INNER * QKVC);
    convert_w_kernel<<<(INNER * INNER + 255) / 256, 256>>>(Wout, wouth, INNER * INNER);
    bias_kernel<<<NNSQ / 256, 256>>>(rel_index, rel_table);

    cudaFuncSetAttribute(gemm_wmma_kernel,
                         cudaFuncAttributeMaxDynamicSharedMemorySize, GEMM_SMEM);
    cudaFuncSetAttribute(attn_mma_kernel,
                         cudaFuncAttributeMaxDynamicSharedMemorySize, ATTN_SMEM);

    // QKV GEMM: [16384,512] @ [512,1536] -> fp16
    {
        dim3 g(QKVC / 128, MTOT / 128);
        gemm_wmma_kernel<<<g, 256, GEMM_SMEM>>>(xh, wqkvh, qkvh, nullptr, nullptr,
                                                QKVC, INNER, 1);
    }
    // attention: 128-row Q tiles
    {
        dim3 g(NTOK / 128, HEADS, NB);
        attn_mma_kernel<<<g, 256, ATTN_SMEM>>>();
    }
    // out projection: [16384,512] @ [512,512] + bias -> fp32
    {
        dim3 g(INNER / 128, MTOT / 128);
        gemm_wmma_kernel<<<g, 256, GEMM_SMEM>>>(atth, wouth, nullptr, out, bout,
                                                INNER, INNER, 0);
    }
}

// round 15
// speedup vs baseline: 1.4878x; 1.0001x over previous
#include <cuda_runtime.h>
#include <cuda_fp16.h>
#include <mma.h>
#include <math.h>
#include <stdint.h>

using namespace nvcuda;

// ---------------- problem constants ----------------
#define NB     16
#define NTOK   1024
#define HEADS  8
#define DHEAD  64
#define INNER  512
#define QKVC   1536
#define NNSQ   (NTOK * NTOK)
#define MTOT   (NB * NTOK)          // 16384
#define SC_LOG2E 0.1803368801111243f   // 0.125 * log2(e)
#define LOG2E    1.4426950408889634f

// ---------------- device scratch ----------------
__device__ __half g_xh   [(size_t)MTOT * INNER];
__device__ __half g_wqkvh[(size_t)INNER * QKVC];
__device__ __half g_wouth[(size_t)INNER * INNER];
__device__ __half g_qkvh [(size_t)MTOT * QKVC];
__device__ __half g_biash[(size_t)HEADS * NNSQ];   // bias * log2(e), fp16
__device__ __half g_atth [(size_t)MTOT * INNER];

// ---------------- helpers ----------------
#define CP_ASYNC16(sa, ga) \
    asm volatile("cp.async.cg.shared.global [%0], [%1], 16;" \
                 :: "r"(sa), "l"(ga) : "memory")
#define CP_COMMIT()  asm volatile("cp.async.commit_group;" ::: "memory")
#define CP_WAIT0()   asm volatile("cp.async.wait_group 0;" ::: "memory")
#define CP_WAIT1()   asm volatile("cp.async.wait_group 1;" ::: "memory")

__device__ __forceinline__ uint32_t s2u(const void* p) {
    return (uint32_t)__cvta_generic_to_shared(p);
}
__device__ __forceinline__ void ldsm_x4(uint32_t* r, uint32_t addr) {
    asm volatile("ldmatrix.sync.aligned.m8n8.x4.shared.b16 {%0,%1,%2,%3}, [%4];"
                 : "=r"(r[0]), "=r"(r[1]), "=r"(r[2]), "=r"(r[3]) : "r"(addr));
}
__device__ __forceinline__ void ldsm_x4_t(uint32_t* r, uint32_t addr) {
    asm volatile("ldmatrix.sync.aligned.m8n8.x4.trans.shared.b16 {%0,%1,%2,%3}, [%4];"
                 : "=r"(r[0]), "=r"(r[1]), "=r"(r[2]), "=r"(r[3]) : "r"(addr));
}
__device__ __forceinline__ void mma16816(float* d, const uint32_t* a, const uint32_t* b) {
    asm volatile(
        "mma.sync.aligned.m16n8k16.row.col.f32.f16.f16.f32 "
        "{%0,%1,%2,%3}, {%4,%5,%6,%7}, {%8,%9}, {%0,%1,%2,%3};"
        : "+f"(d[0]), "+f"(d[1]), "+f"(d[2]), "+f"(d[3])
        : "r"(a[0]), "r"(a[1]), "r"(a[2]), "r"(a[3]), "r"(b[0]), "r"(b[1]));
}
__device__ __forceinline__ uint32_t h2ex2(uint32_t x) {
    uint32_t r;
    asm("ex2.approx.f16x2 %0, %1;" : "=r"(r) : "r"(x));
    return r;
}

// ---------------- fused prep kernel (one launch) ----------------
// block ranges: [0, 32768) convert x | [32768, 34304) Wqkv | [34304, 34816) Wout
//               [34816, 38912) bias gather
#define PREP_X_BLKS   32768
#define PREP_WQ_BLKS  1536
#define PREP_WO_BLKS  512
#define PREP_BIAS_BLKS 4096
#define PREP_TOTAL (PREP_X_BLKS + PREP_WQ_BLKS + PREP_WO_BLKS + PREP_BIAS_BLKS)

__global__ void prep_kernel(const float* __restrict__ x,
                            const float* __restrict__ Wqkv,
                            const float* __restrict__ Wout,
                            const int* __restrict__ ri,
                            const float* __restrict__ rt) {
    int blk = blockIdx.x;
    if (blk < PREP_X_BLKS) {
        size_t i = (size_t)blk * 256 + threadIdx.x;
        float2 v = ((const float2*)x)[i];
        ((__half2*)g_xh)[i] = __floats2half2_rn(v.x, v.y);
    } else if (blk < PREP_X_BLKS + PREP_WQ_BLKS) {
        size_t i = (size_t)(blk - PREP_X_BLKS) * 256 + threadIdx.x;
        float2 v = ((const float2*)Wqkv)[i];
        ((__half2*)g_wqkvh)[i] = __floats2half2_rn(v.x, v.y);
    } else if (blk < PREP_X_BLKS + PREP_WQ_BLKS + PREP_WO_BLKS) {
        size_t i = (size_t)(blk - PREP_X_BLKS - PREP_WQ_BLKS) * 256 + threadIdx.x;
        float2 v = ((const float2*)Wout)[i];
        ((__half2*)g_wouth)[i] = __floats2half2_rn(v.x, v.y);
    } else {
        int t = (blk - PREP_X_BLKS - PREP_WQ_BLKS - PREP_WO_BLKS) * 256 + threadIdx.x;
        int idx = ri[t];
        #pragma unroll
        for (int h = 0; h < HEADS; h++)
            g_biash[(size_t)h * NNSQ + t] = __float2half(rt[idx * HEADS + h] * LOG2E);
    }
}

// ---------------- wmma GEMM, 3-stage cp.async ring ----------------
#define ALD 72
#define BLD 136
#define AS_STAGE (128 * ALD)
#define BS_STAGE (64 * BLD)
#define GEMM_SMEM (3 * (AS_STAGE + BS_STAGE) * 2)   // 107520 B

__global__ __launch_bounds__(256)
void gemm_wmma_kernel(const __half* __restrict__ A, const __half* __restrict__ B,
                      __half* __restrict__ Ch, float* __restrict__ Cf,
                      const float* __restrict__ bias, int Nn, int K, int outHalf) {
    extern __shared__ __half sm[];
    __half* As = sm;
    __half* Bs = sm + 3 * AS_STAGE;
    float*  buf = (float*)sm;

    const int tid = threadIdx.x, wid = tid >> 5, lane = tid & 31;
    const int wm = wid & 3, wn = wid >> 2;
    const int m0 = blockIdx.y * 128, n0 = blockIdx.x * 128;
    const int nStages = K / 64;

    wmma::fragment<wmma::accumulator, 16, 16, 16, float> c[2][4];
    #pragma unroll
    for (int i = 0; i < 2; i++)
        #pragma unroll
        for (int j = 0; j < 4; j++) wmma::fill_fragment(c[i][j], 0.0f);

    auto loadTiles = [&](int st, int kb) {
        __half* as = As + st * AS_STAGE;
        __half* bs = Bs + st * BS_STAGE;
        #pragma unroll
        for (int i = tid; i < 1024; i += 256) {
            int r = i >> 3, cc = (i & 7) * 8;
            CP_ASYNC16(s2u(as + r * ALD + cc),
                       A + (size_t)(m0 + r) * K + kb + cc);
        }
        #pragma unroll
        for (int i = tid; i < 1024; i += 256) {
            int r = i >> 4, cc = (i & 15) * 8;
            CP_ASYNC16(s2u(bs + r * BLD + cc),
                       B + (size_t)(kb + r) * Nn + n0 + cc);
        }
        CP_COMMIT();
    };

    loadTiles(0, 0);
    loadTiles(1, 64);
    for (int s = 0; s < nStages; s++) {
        if (s + 1 < nStages) CP_WAIT1(); else CP_WAIT0();
        __syncthreads();
        if (s + 2 < nStages) loadTiles((s + 2) % 3, (s + 2) * 64);

        const __half* as = As + (s % 3) * AS_STAGE;
        const __half* bs = Bs + (s % 3) * BS_STAGE;
        #pragma unroll
        for (int kk = 0; kk < 4; kk++) {
            wmma::fragment<wmma::matrix_a, 16, 16, 16, __half, wmma::row_major> a[2];
            wmma::fragment<wmma::matrix_b, 16, 16, 16, __half, wmma::row_major> bfr[4];
            #pragma unroll
            for (int i = 0; i < 2; i++)
                wmma::load_matrix_sync(a[i], &as[(wm * 32 + i * 16) * ALD + kk * 16], ALD);
            #pragma unroll
            for (int j = 0; j < 4; j++)
                wmma::load_matrix_sync(bfr[j], &bs[(kk * 16) * BLD + wn * 64 + j * 16], BLD);
            #pragma unroll
            for (int i = 0; i < 2; i++)
                #pragma unroll
                for (int j = 0; j < 4; j++)
                    wmma::mma_sync(c[i][j], a[i], bfr[j], c[i][j]);
        }
    }
    __syncthreads();

    float* mybuf = buf + wid * 16 * 20;
    #pragma unroll
    for (int i = 0; i < 2; i++) {
        #pragma unroll
        for (int j = 0; j < 4; j++) {
            wmma::store_matrix_sync(mybuf, c[i][j], 20, wmma::mem_row_major);
            __syncwarp();
            int r   = lane >> 1;
            int cl  = (lane & 1) * 8;
            int row = m0 + wm * 32 + i * 16 + r;
            int col = n0 + wn * 64 + j * 16 + cl;
            const float* src = &mybuf[r * 20 + cl];
            if (outHalf) {
                __half2 h2[4];
                #pragma unroll
                for (int q = 0; q < 4; q++)
                    h2[q] = __floats2half2_rn(src[2 * q], src[2 * q + 1]);
                *(float4*)(Ch + (size_t)row * Nn + col) = *(float4*)h2;
            } else {
                float v[8];
                #pragma unroll
                for (int q = 0; q < 8; q++) v[q] = src[q] + bias[col + q];
                float* dst = Cf + (size_t)row * Nn + col;
                *(float4*)dst = *(float4*)v;
                *(float4*)(dst + 4) = *(float4*)(v + 4);
            }
            __syncwarp();
        }
    }
}

// ---------------- flash attention: 128-row Q, 3-stage KV ring ----------------
#define KLD 72
#define KV_STAGE (64 * KLD)
#define ATTN_SMEM (3 * 2 * KV_STAGE * 2)    // 55296 B

__global__ __launch_bounds__(256)
void attn_mma_kernel() {
    extern __shared__ __half asm_[];
    __half* Ks = asm_;
    __half* Vs = asm_ + 3 * KV_STAGE;

    const int qt = blockIdx.x, h = blockIdx.y, b = blockIdx.z;
    const int q0 = qt * 128;
    const int tid = threadIdx.x, wq = tid >> 5, lane = tid & 31;
    const int g = lane >> 2, tig = lane & 3;

    // ---- Q fragments (A operand) from gmem ----
    uint32_t aQ[4][4];
    {
        const __half* q0p = g_qkvh + (size_t)(b * NTOK + q0 + wq * 16 + g) * QKVC + h * DHEAD;
        const __half* q8p = q0p + (size_t)8 * QKVC;
        #pragma unroll
        for (int kc = 0; kc < 4; kc++) {
            aQ[kc][0] = *(const uint32_t*)(q0p + kc * 16 + tig * 2);
            aQ[kc][1] = *(const uint32_t*)(q8p + kc * 16 + tig * 2);
            aQ[kc][2] = *(const uint32_t*)(q0p + kc * 16 + 8 + tig * 2);
            aQ[kc][3] = *(const uint32_t*)(q8p + kc * 16 + 8 + tig * 2);
        }
    }

    float o[8][4];
    #pragma unroll
    for (int i = 0; i < 8; i++)
        #pragma unroll
        for (int j = 0; j < 4; j++) o[i][j] = 0.f;
    float l0 = 0.f, l1 = 0.f;

    const __half* bias0 = g_biash + ((size_t)h << 20)
                        + (size_t)(q0 + wq * 16 + g) * NTOK;
    const __half* bias8 = bias0 + (size_t)8 * NTOK;

    const int kRow = (lane & 7) + ((lane >> 4) << 3);
    const int kColH = ((lane >> 3) & 1) * 8;
    const int vRowOff = ((lane >> 3) & 1) * 8 + (lane & 7);
    const int vColH = (lane >> 4) * 8;

    auto ldKV = [&](int st, int k0) {
        #pragma unroll
        for (int i = tid; i < 512; i += 256) {
            int r = i >> 3, cc = (i & 7) * 8;
            const __half* gk = g_qkvh + (size_t)(b * NTOK + k0 + r) * QKVC
                             + INNER + h * DHEAD + cc;
            CP_ASYNC16(s2u(&Ks[st * KV_STAGE + r * KLD + cc]), gk);
            CP_ASYNC16(s2u(&Vs[st * KV_STAGE + r * KLD + cc]), gk + INNER);
        }
        CP_COMMIT();
    };

    ldKV(0, 0);
    ldKV(1, 64);
    for (int kt = 0; kt < 16; kt++) {
        const int k0 = kt * 64;
        if (kt + 1 < 16) CP_WAIT1(); else CP_WAIT0();
        __syncthreads();
        if (kt + 2 < 16) ldKV((kt + 2) % 3, (kt + 2) * 64);
        const __half* ks = Ks + (kt % 3) * KV_STAGE;
        const __half* vs = Vs + (kt % 3) * KV_STAGE;

        // ---- prefetch bias (latency hides under MMA1) ----
        __half2 c0[8], c8[8];
        #pragma unroll
        for (int nt = 0; nt < 8; nt++) {
            c0[nt] = *(const __half2*)(bias0 + k0 + nt * 8 + tig * 2);
            c8[nt] = *(const __half2*)(bias8 + k0 + nt * 8 + tig * 2);
        }

        // ---- S = Q @ K^T ----
        float cS[8][4];
        #pragma unroll
        for (int nt = 0; nt < 8; nt++)
            #pragma unroll
            for (int j = 0; j < 4; j++) cS[nt][j] = 0.f;

        #pragma unroll
        for (int kc = 0; kc < 4; kc++) {
            #pragma unroll
            for (int nt2 = 0; nt2 < 4; nt2++) {
                uint32_t r4[4];
                ldsm_x4(r4, s2u(&ks[(nt2 * 16 + kRow) * KLD + kc * 16 + kColH]));
                mma16816(cS[nt2 * 2],     aQ[kc], r4);
                mma16816(cS[nt2 * 2 + 1], aQ[kc], r4 + 2);
            }
        }

        // ---- scale + bias + f16x2 ex2, pack P A-fragments ----
        uint32_t pa[4][4];
        __half2 acc0 = __floats2half2_rn(0.f, 0.f);
        __half2 acc1 = acc0;
        #pragma unroll
        for (int nt = 0; nt < 8; nt++) {
            float f0 = fmaf(cS[nt][0], SC_LOG2E, __low2float(c0[nt]));
            float f1 = fmaf(cS[nt][1], SC_LOG2E, __high2float(c0[nt]));
            float f2 = fmaf(cS[nt][2], SC_LOG2E, __low2float(c8[nt]));
            float f3 = fmaf(cS[nt][3], SC_LOG2E, __high2float(c8[nt]));
            __half2 x01 = __floats2half2_rn(f0, f1);
            __half2 x23 = __floats2half2_rn(f2, f3);
            uint32_t e01 = h2ex2(*(uint32_t*)&x01);
            uint32_t e23 = h2ex2(*(uint32_t*)&x23);
            acc0 = __hadd2(acc0, *(__half2*)&e01);
            acc1 = __hadd2(acc1, *(__half2*)&e23);
            pa[nt >> 1][(nt & 1) * 2 + 0] = e01;
            pa[nt >> 1][(nt & 1) * 2 + 1] = e23;
        }
        float2 s0 = __half22float2(acc0);
        float2 s1 = __half22float2(acc1);
        l0 += s0.x + s0.y;
        l1 += s1.x + s1.y;

        // ---- O += P @ V ----
        #pragma unroll
        for (int kc = 0; kc < 4; kc++) {
            #pragma unroll
            for (int dt2 = 0; dt2 < 4; dt2++) {
                uint32_t r4[4];
                ldsm_x4_t(r4, s2u(&vs[(kc * 16 + vRowOff) * KLD + dt2 * 16 + vColH]));
                mma16816(o[dt2 * 2],     pa[kc], r4);
                mma16816(o[dt2 * 2 + 1], pa[kc], r4 + 2);
            }
        }
    }

    // ---- row sums across the 4 lanes of each group ----
    l0 += __shfl_xor_sync(0xffffffffu, l0, 1);
    l0 += __shfl_xor_sync(0xffffffffu, l0, 2);
    l1 += __shfl_xor_sync(0xffffffffu, l1, 1);
    l1 += __shfl_xor_sync(0xffffffffu, l1, 2);
    const float inv0 = 1.0f / l0, inv1 = 1.0f / l1;

    // ---- write O (fp16) ----
    __half* out0 = g_atth + (size_t)(b * NTOK + q0 + wq * 16 + g) * INNER + h * DHEAD;
    __half* out8 = out0 + (size_t)8 * INNER;
    #pragma unroll
    for (int dt = 0; dt < 8; dt++) {
        __half2 r0 = __floats2half2_rn(o[dt][0] * inv0, o[dt][1] * inv0);
        __half2 r8 = __floats2half2_rn(o[dt][2] * inv1, o[dt][3] * inv1);
        *(__half2*)(out0 + dt * 8 + tig * 2) = r0;
        *(__half2*)(out8 + dt * 8 + tig * 2) = r8;
    }
}

// ---------------- launch ----------------
extern "C" void kernel_launch(void* const* d_in, const int* in_sizes, int n_in,
                              void* d_out, int out_size) {
    const float* x         = (const float*)d_in[0];
    const float* Wqkv      = (const float*)d_in[1];
    const float* rel_table = (const float*)d_in[2];
    const float* Wout      = (const float*)d_in[3];
    const float* bout      = (const float*)d_in[4];
    const int*   rel_index = (const int*)d_in[5];
    float*       out       = (float*)d_out;

    __half *xh, *wqkvh, *wouth, *qkvh, *atth;
    cudaGetSymbolAddress((void**)&xh,    g_xh);
    cudaGetSymbolAddress((void**)&wqkvh, g_wqkvh);
    cudaGetSymbolAddress((void**)&wouth, g_wouth);
    cudaGetSymbolAddress((void**)&qkvh,  g_qkvh);
    cudaGetSymbolAddress((void**)&atth,  g_atth);

    prep_kernel<<<PREP_TOTAL, 256>>>(x, Wqkv, Wout, rel_index, rel_table);

    cudaFuncSetAttribute(gemm_wmma_kernel,
                         cudaFuncAttributeMaxDynamicSharedMemorySize, GEMM_SMEM);
    cudaFuncSetAttribute(attn_mma_kernel,
                         cudaFuncAttributeMaxDynamicSharedMemorySize, ATTN_SMEM);

    // QKV GEMM: [16384,512] @ [512,1536] -> fp16
    {
        dim3 g(QKVC / 128, MTOT / 128);
        gemm_wmma_kernel<<<g, 256, GEMM_SMEM>>>(xh, wqkvh, qkvh, nullptr, nullptr,
                                                QKVC, INNER, 1);
    }
    // attention: 128-row Q tiles
    {
        dim3 g(NTOK / 128, HEADS, NB);
        attn_mma_kernel<<<g, 256, ATTN_SMEM>>>();
    }
    // out projection: [16384,512] @ [512,512] + bias -> fp32
    {
        dim3 g(INNER / 128, MTOT / 128);
        gemm_wmma_kernel<<<g, 256, GEMM_SMEM>>>(atth, wouth, nullptr, out, bout,
                                                INNER, INNER, 0);
    }
}